// round 2
// baseline (speedup 1.0000x reference)
#include <cuda_runtime.h>
#include <stdint.h>

#define FULLMASK 0xffffffffu

// ---------------- scratch (device globals; no allocation allowed) ----------------
__device__ __align__(16) uint32_t g_A2[128*32*32*4];   // packed acts into layer2 (32x32, 128ch)
__device__ __align__(16) uint32_t g_A3[128*16*16*4];   // into layer3 (16x16, 128ch)
__device__ __align__(16) uint32_t g_A4[128*16*16*8];   // into layer4 (16x16, 256ch)
__device__ __align__(16) uint32_t g_A5[128*8*8*8];     // into layer5 (8x8, 256ch)
__device__ __align__(16) uint32_t g_A6[128*8*8*16];    // into layer6 (8x8, 512ch)
__device__ __align__(16) float    g_H6[128*4*4*512];   // float acts after layer6 pool+bn
// weights packed cout-major: wp[cout*(9*NW) + tap*NW + wd]
__device__ __align__(16) uint32_t g_W2[128*9*4];
__device__ __align__(16) uint32_t g_W3[256*9*4];
__device__ __align__(16) uint32_t g_W4[256*9*8];
__device__ __align__(16) uint32_t g_W5[512*9*8];
__device__ __align__(16) uint32_t g_W6[512*9*16];

// ---------------- merged weight sign-packing ----------------
// bit b of word wd <-> cin = wd*32+b, bit=1 <=> w>0
__global__ void pack_all_kernel(const float* __restrict__ w2, const float* __restrict__ w3,
                                const float* __restrict__ w4, const float* __restrict__ w5,
                                const float* __restrict__ w6)
{
    int idx = blockIdx.x * blockDim.x + threadIdx.x;
    const float* w; uint32_t* wp; int words, Cout, o;
    if      (idx <   4608) { w = w2; wp = g_W2; words = 4;  Cout = 128; o = idx; }
    else if (idx <  13824) { w = w3; wp = g_W3; words = 4;  Cout = 256; o = idx - 4608; }
    else if (idx <  32256) { w = w4; wp = g_W4; words = 8;  Cout = 256; o = idx - 13824; }
    else if (idx <  69120) { w = w5; wp = g_W5; words = 8;  Cout = 512; o = idx - 32256; }
    else if (idx < 142848) { w = w6; wp = g_W6; words = 16; Cout = 512; o = idx - 69120; }
    else return;
    int cout = o % Cout;
    int j    = o / Cout;          // tap*words + wd
    int wd   = j % words;
    int tap  = j / words;
    int Cin  = words * 32;
    const float* base = w + ((size_t)tap * Cin + (size_t)wd * 32) * Cout + cout;
    uint32_t bits = 0;
    for (int bb = 0; bb < 32; ++bb)
        if (base[(size_t)bb * Cout] > 0.f) bits |= (1u << bb);
    wp[(size_t)cout * (9 * words) + j] = bits;
}

// ---------------- layer 1: float conv 3->128 + relu + b1 + bn1 + binarize-pack ----------------
__global__ __launch_bounds__(128) void conv1_kernel(
    const float* __restrict__ x, const float* __restrict__ w1,
    const float* __restrict__ b1, const float* __restrict__ sc1,
    const float* __restrict__ bi1)
{
    __shared__ float xs[3 * 34 * 3];   // 3 rows, cols -1..32 zero-padded, 3 ch
    const int tid = threadIdx.x;
    const int y = blockIdx.x, b = blockIdx.y;

    for (int i = tid; i < 3 * 34 * 3; i += 128) xs[i] = 0.f;
    __syncthreads();
    for (int j = 0; j < 3; ++j) {
        int gy = y + j - 1;
        if (gy < 0 || gy >= 32) continue;
        if (tid < 96) {
            int c = tid / 3, ci = tid % 3;
            xs[(j * 34 + c + 1) * 3 + ci] = x[((size_t)(b * 32 + gy) * 32 + c) * 3 + ci];
        }
    }
    __syncthreads();

    float wr[27];
    #pragma unroll
    for (int k = 0; k < 27; ++k) wr[k] = w1[k * 128 + tid];
    const float bv = b1[tid], scv = sc1[tid], biv = bi1[tid];
    const int lane = tid & 31, warp = tid >> 5;

    for (int c = 0; c < 32; ++c) {
        float sum = 0.f;
        #pragma unroll
        for (int ky = 0; ky < 3; ++ky)
            #pragma unroll
            for (int kx = 0; kx < 3; ++kx)
                #pragma unroll
                for (int ci = 0; ci < 3; ++ci)
                    sum += xs[(ky * 34 + c + kx) * 3 + ci] * wr[(ky * 3 + kx) * 3 + ci];
        float h = fmaxf(sum + bv, 0.f);
        float f = __fadd_rn(__fmul_rn(h, scv), biv);
        unsigned bits = __ballot_sync(FULLMASK, f > 0.f);
        if (lane == 0) g_A2[((size_t)(b * 32 + y) * 32 + c) * 4 + warp] = bits;
    }
}

// ---------------- CSA popcount compressors ----------------
__device__ __forceinline__ void FA(uint32_t a, uint32_t b, uint32_t c,
                                   uint32_t& s, uint32_t& cy) {
    s  = a ^ b ^ c;
    cy = (a & b) | (a & c) | (b & c);
}

// popcount of 8 masked-xored words: words 0..3 mask ma, words 4..7 mask mb
__device__ __forceinline__ int comp8m(const uint32_t* __restrict__ ap,
                                      const uint32_t* __restrict__ w,
                                      uint32_t ma, uint32_t mb) {
    uint4 x = *reinterpret_cast<const uint4*>(ap);
    uint4 y = *reinterpret_cast<const uint4*>(ap + 4);
    uint32_t e0 = (x.x ^ w[0]) & ma, e1 = (x.y ^ w[1]) & ma;
    uint32_t e2 = (x.z ^ w[2]) & ma, e3 = (x.w ^ w[3]) & ma;
    uint32_t e4 = (y.x ^ w[4]) & mb, e5 = (y.y ^ w[5]) & mb;
    uint32_t e6 = (y.z ^ w[6]) & mb, e7 = (y.w ^ w[7]) & mb;
    uint32_t s1, c1, s2, c2, s3, c3, s4, c4;
    FA(e0, e1, e2, s1, c1);
    FA(e3, e4, e5, s2, c2);
    FA(s1, s2, e6, s3, c3);
    FA(c1, c2, c3, s4, c4);
    return __popc(s3) + __popc(e7) + 2 * __popc(s4) + 4 * __popc(c4);
}

__device__ __forceinline__ int comp4m(const uint32_t* __restrict__ ap,
                                      const uint32_t* __restrict__ w, uint32_t m) {
    uint4 x = *reinterpret_cast<const uint4*>(ap);
    uint32_t e0 = (x.x ^ w[0]) & m, e1 = (x.y ^ w[1]) & m;
    uint32_t e2 = (x.z ^ w[2]) & m, e3 = (x.w ^ w[3]) & m;
    uint32_t s, cy;
    FA(e0, e1, e2, s, cy);
    return __popc(s) + __popc(e3) + 2 * __popc(cy);
}

// conv at one pixel (r in {0,1} within the 2-row tile, column c), fully runtime-indexed.
// sm: staged 4 x (W+2)*NW halo image; wr: 9*NW weight words in regs; rmask: bit j = row j valid
template <int W, int NW>
__device__ __forceinline__ int conv_px(const uint32_t* __restrict__ sm,
                                       const uint32_t* __restrict__ wr,
                                       uint32_t rmask, int r, int c)
{
    constexpr int RWH = (W + 2) * NW;
    const uint32_t mc0 = (c > 0)     ? 0xffffffffu : 0u;
    const uint32_t mc2 = (c < W - 1) ? 0xffffffffu : 0u;
    const uint32_t* rp0 = sm + r * RWH + c * NW;
    int acc = 0;
    #pragma unroll
    for (int ky = 0; ky < 3; ++ky) {
        const uint32_t mr = (uint32_t)(-(int)((rmask >> (r + ky)) & 1u));
        const uint32_t* rp = rp0 + ky * RWH;
        const uint32_t* wt = wr + ky * 3 * NW;
        if constexpr (NW == 4) {
            acc += comp8m(rp, wt, mr & mc0, mr);           // taps kx=0,1
            acc += comp4m(rp + 8, wt + 8, mr & mc2);       // tap kx=2
        } else if constexpr (NW == 8) {
            uint32_t m0 = mr & mc0, m2 = mr & mc2;
            acc += comp8m(rp,      wt,      m0, m0);
            acc += comp8m(rp + 8,  wt + 8,  mr, mr);
            acc += comp8m(rp + 16, wt + 16, m2, m2);
        } else {  // NW == 16
            uint32_t m0 = mr & mc0, m2 = mr & mc2;
            acc += comp8m(rp,      wt,      m0, m0) + comp8m(rp + 8,  wt + 8,  m0, m0);
            acc += comp8m(rp + 16, wt + 16, mr, mr) + comp8m(rp + 24, wt + 24, mr, mr);
            acc += comp8m(rp + 32, wt + 32, m2, m2) + comp8m(rp + 40, wt + 40, m2, m2);
        }
    }
    return acc;
}

// ---------------- generic binary conv (XNOR + CSA popcount) ----------------
// block: 128 threads = 128 consecutive output channels
// grid: (H/2 row-tiles, COUT/128 chunks, 128 batch)
template <int H, int W, int NW, int CIN, int COUT, bool POOL, bool FOUT>
__device__ __forceinline__ void binconv_body(
    const uint32_t* __restrict__ A, const uint32_t* __restrict__ Wp,
    const float* __restrict__ scale, const float* __restrict__ bias,
    uint32_t* __restrict__ Aout, float* __restrict__ Fout)
{
    constexpr int RWH = (W + 2) * NW;
    __shared__ __align__(16) uint32_t s[4 * RWH];
    const int tid = threadIdx.x;
    const int t   = blockIdx.x;
    const int b   = blockIdx.z;
    const int cout = blockIdx.y * 128 + tid;
    const int y0  = 2 * t;

    // all 9 taps' weight words register-resident for this cout
    uint32_t wr[9 * NW];
    {
        const uint4* wv = reinterpret_cast<const uint4*>(Wp + (size_t)cout * 9 * NW);
        #pragma unroll
        for (int i = 0; i < 9 * NW / 4; ++i)
            reinterpret_cast<uint4*>(wr)[i] = wv[i];
    }

    // stage rows [y0-1, y0+2] with one packed-pixel halo on each side (zero-filled)
    for (int idx = tid; idx < 4 * RWH; idx += 128) {
        int j = idx / RWH, k = idx - j * RWH;
        int gy = y0 - 1 + j;
        uint32_t v = 0;
        if ((unsigned)gy < (unsigned)H && k >= NW && k < RWH - NW)
            v = A[((size_t)(b * H + gy) * W) * NW + (k - NW)];
        s[idx] = v;
    }
    __syncthreads();

    uint32_t rmask = 0;
    #pragma unroll
    for (int j = 0; j < 4; ++j) {
        int gy = y0 - 1 + j;
        if ((unsigned)gy < (unsigned)H) rmask |= 1u << j;
    }

    const float scv = scale[cout], biv = bias[cout];
    const int lane = tid & 31;
    const int widx = blockIdx.y * 4 + (tid >> 5);
    constexpr int NWOUT = COUT / 32;

    auto cval = [&](int r, int c, int acc) -> int {
        int gy = y0 + r;
        int nv = (3 - (gy == 0) - (gy == H - 1)) * (3 - (c == 0) - (c == W - 1));
        int v = CIN * nv - 2 * acc;   // exact conv sum over valid taps
        return v > 0 ? v : 0;         // relu
    };

    if constexpr (POOL) {
        for (int oc = 0; oc < W / 2; ++oc) {
            int c0 = 2 * oc, c1 = c0 + 1;
            int a00 = conv_px<W, NW>(s, wr, rmask, 0, c0);
            int a01 = conv_px<W, NW>(s, wr, rmask, 0, c1);
            int a10 = conv_px<W, NW>(s, wr, rmask, 1, c0);
            int a11 = conv_px<W, NW>(s, wr, rmask, 1, c1);
            int m = max(max(cval(0, c0, a00), cval(0, c1, a01)),
                        max(cval(1, c0, a10), cval(1, c1, a11)));
            float f = __fadd_rn(__fmul_rn((float)m, scv), biv);
            if constexpr (FOUT) {
                Fout[((size_t)(b * (H / 2) + t) * (W / 2) + oc) * COUT + cout] = f;
            } else {
                unsigned bits = __ballot_sync(FULLMASK, f > 0.f);
                if (lane == 0)
                    Aout[((size_t)(b * (H / 2) + t) * (W / 2) + oc) * NWOUT + widx] = bits;
            }
        }
    } else {
        #pragma unroll
        for (int r = 0; r < 2; ++r) {
            int gy = y0 + r;
            for (int c = 0; c < W; ++c) {
                int a = conv_px<W, NW>(s, wr, rmask, r, c);
                int v = cval(r, c, a);
                float f = __fadd_rn(__fmul_rn((float)v, scv), biv);
                unsigned bits = __ballot_sync(FULLMASK, f > 0.f);
                if (lane == 0)
                    Aout[((size_t)(b * H + gy) * W + c) * NWOUT + widx] = bits;
            }
        }
    }
}

__global__ __launch_bounds__(128) void l2_kernel(const float* sc, const float* bi) {
    binconv_body<32, 32, 4, 128, 128, true,  false>(g_A2, g_W2, sc, bi, g_A3, nullptr);
}
__global__ __launch_bounds__(128) void l3_kernel(const float* sc, const float* bi) {
    binconv_body<16, 16, 4, 128, 256, false, false>(g_A3, g_W3, sc, bi, g_A4, nullptr);
}
__global__ __launch_bounds__(128) void l4_kernel(const float* sc, const float* bi) {
    binconv_body<16, 16, 8, 256, 256, true,  false>(g_A4, g_W4, sc, bi, g_A5, nullptr);
}
__global__ __launch_bounds__(128) void l5_kernel(const float* sc, const float* bi) {
    binconv_body<8, 8, 8, 256, 512, false, false>(g_A5, g_W5, sc, bi, g_A6, nullptr);
}
__global__ __launch_bounds__(128) void l6_kernel(const float* sc, const float* bi) {
    binconv_body<8, 8, 16, 512, 512, true, true>(g_A6, g_W6, sc, bi, nullptr, g_H6);
}

// ---------------- dense (512->10) + softmax, one warp per pixel ----------------
__global__ __launch_bounds__(128) void dense_kernel(
    const float* __restrict__ dw, const float* __restrict__ db, float* __restrict__ out)
{
    __shared__ float sdw[512 * 10];   // transposed: sdw[d*512 + c]
    const int tid = threadIdx.x;
    for (int i = tid; i < 5120; i += 128) {
        int c = i / 10, d = i % 10;
        sdw[d * 512 + c] = dw[i];
    }
    __syncthreads();
    const int warp = tid >> 5, lane = tid & 31;
    const int p = blockIdx.x * 4 + warp;   // pixel in [0, 2048)
    float lg[10];
    #pragma unroll
    for (int d = 0; d < 10; ++d) lg[d] = 0.f;
    for (int c = lane; c < 512; c += 32) {
        float h = g_H6[(size_t)p * 512 + c];
        #pragma unroll
        for (int d = 0; d < 10; ++d) lg[d] += h * sdw[d * 512 + c];
    }
    #pragma unroll
    for (int d = 0; d < 10; ++d)
        for (int off = 16; off; off >>= 1)
            lg[d] += __shfl_xor_sync(FULLMASK, lg[d], off);
    if (lane == 0) {
        float l[10], mx = -1e30f;
        #pragma unroll
        for (int d = 0; d < 10; ++d) { l[d] = lg[d] + db[d]; mx = fmaxf(mx, l[d]); }
        float e[10], ssum = 0.f;
        #pragma unroll
        for (int d = 0; d < 10; ++d) { e[d] = expf(l[d] - mx); ssum += e[d]; }
        float inv = 1.f / ssum;
        #pragma unroll
        for (int d = 0; d < 10; ++d) out[(size_t)p * 10 + d] = e[d] * inv;
    }
}

// ---------------- launch ----------------
extern "C" void kernel_launch(void* const* d_in, const int* in_sizes, int n_in,
                              void* d_out, int out_size)
{
    const float* P[22];
    for (int i = 0; i < 22 && i < n_in; ++i) P[i] = (const float*)d_in[i];

    const float *x, *w1, *b1, *w2, *w3, *w4, *w5, *w6;
    const float *bn1s, *bn1b, *bn2s, *bn2b, *bn3s, *bn3b, *bn4s, *bn4b, *bn5s, *bn5b, *bn6s, *bn6b;
    const float *dw, *db;

    if (in_sizes[3] == 147456) {
        // setup_inputs dict order
        x = P[0];  w1 = P[1]; b1 = P[2];
        w2 = P[3]; w3 = P[4]; w4 = P[5]; w5 = P[6]; w6 = P[7];
        bn1s = P[8];  bn1b = P[9];  bn2s = P[10]; bn2b = P[11];
        bn3s = P[12]; bn3b = P[13]; bn4s = P[14]; bn4b = P[15];
        bn5s = P[16]; bn5b = P[17]; bn6s = P[18]; bn6b = P[19];
        dw = P[20]; db = P[21];
    } else {
        // reference() signature order
        x = P[0];  w1 = P[1]; b1 = P[2]; bn1s = P[3]; bn1b = P[4];
        w2 = P[5];  bn2s = P[6];  bn2b = P[7];
        w3 = P[8];  bn3s = P[9];  bn3b = P[10];
        w4 = P[11]; bn4s = P[12]; bn4b = P[13];
        w5 = P[14]; bn5s = P[15]; bn5b = P[16];
        w6 = P[17]; bn6s = P[18]; bn6b = P[19];
        dw = P[20]; db = P[21];
    }

    // merged weight sign-packing (one launch)
    pack_all_kernel<<<(142848 + 255) / 256, 256>>>(w2, w3, w4, w5, w6);

    // layer 1 (float conv) -> packed bits
    conv1_kernel<<<dim3(32, 128), 128>>>(x, w1, b1, bn1s, bn1b);

    // binary layers
    l2_kernel<<<dim3(16, 1, 128), 128>>>(bn2s, bn2b);
    l3_kernel<<<dim3(8, 2, 128), 128>>>(bn3s, bn3b);
    l4_kernel<<<dim3(8, 2, 128), 128>>>(bn4s, bn4b);
    l5_kernel<<<dim3(4, 4, 128), 128>>>(bn5s, bn5b);
    l6_kernel<<<dim3(4, 4, 128), 128>>>(bn6s, bn6b);

    // dense + softmax
    dense_kernel<<<512, 128>>>(dw, db, (float*)d_out);
}